// round 4
// baseline (speedup 1.0000x reference)
#include <cuda_runtime.h>
#include <math.h>
#include <stdint.h>

// ---------------------------------------------------------------------------
// TrAISformer forward. Big GEMMs on tcgen05 (tf32, SS mode, TMEM accum) when
// compiled for sm_103a/f; mma.sync TF32 fallback for the featureless pass.
// B=64, T=256, D=768, H=12, HD=64, L=12, FFN=3072, OUT=302. M = B*T = 16384.
// ---------------------------------------------------------------------------

#if defined(__CUDA_ARCH__) && (defined(__CUDA_ARCH_FEAT_SM103_ALL) || \
    (defined(__CUDA_ARCH_SPECIFIC__) && (__CUDA_ARCH_SPECIFIC__ == 1030)) || \
    (defined(__CUDA_ARCH_FAMILY_SPECIFIC__) && (__CUDA_ARCH_FAMILY_SPECIFIC__ == 1030)))
#define HAS_TCGEN05 1
#else
#define HAS_TCGEN05 0
#endif

#define M_ROWS   16384
#define DMODEL   768
#define NHEAD    12
#define HDIM     64
#define NLAYER   12
#define DFF      3072
#define NOUT     302
#define SEQ      256

__device__ float g_h[M_ROWS * DMODEL];
__device__ float g_x[M_ROWS * DMODEL];
__device__ float g_q[M_ROWS * DMODEL];
__device__ float g_k[M_ROWS * DMODEL];
__device__ float g_v[M_ROWS * DMODEL];
__device__ float g_y[M_ROWS * DMODEL];
__device__ float g_s[50331648];
// transposed (K-major, tf32-rounded) weights: Wq,Wk,Wv,Wo (4 x 12 x 768x768),
// then W1 (12 x 3072x768), then W2 (12 x 768x3072)
__device__ float g_wt[84934656];

__device__ __forceinline__ float gelu_f(float v) {
    return 0.5f * v * (1.0f + erff(v * 0.70710678118654752f));
}

__device__ __forceinline__ uint32_t rna_tf32(float x) {
    uint32_t u;
    asm("cvt.rna.tf32.f32 %0, %1;" : "=r"(u) : "f"(x));
    return u;
}

__device__ __forceinline__ uint32_t smem_u32(const void* p) {
    uint32_t a;
    asm("{ .reg .u64 t; cvta.to.shared.u64 t, %1; cvt.u32.u64 %0, t; }" : "=r"(a) : "l"(p));
    return a;
}

#if HAS_TCGEN05
__device__ __forceinline__ uint32_t elect_one_pred() {
    uint32_t pred;
    asm volatile(
        "{\n\t.reg .pred p;\n\telect.sync _|p, 0xFFFFFFFF;\n\tselp.b32 %0, 1, 0, p;\n\t}"
        : "=r"(pred));
    return pred;
}

__device__ __forceinline__ uint64_t make_desc_sw128(uint32_t addr) {
    const uint64_t base = (uint64_t(2) << 61) | (uint64_t(1) << 46) |
                          (uint64_t(64) << 32) | (uint64_t(1) << 16);
    return base | ((addr >> 4) & 0x3FFF);
}

__device__ __forceinline__ void mma_tf32_ss(uint32_t d, uint64_t ad, uint64_t bd,
                                            uint32_t idesc, uint32_t en) {
    uint32_t z = 0;
    asm volatile(
        "{\n\t"
        ".reg .pred p;\n\t"
        "setp.ne.u32 p, %5, 0;\n\t"
        "tcgen05.mma.cta_group::1.kind::tf32 [%0], %1, %2, %3, {%4, %4, %4, %4}, p;\n\t"
        "}"
        :: "r"(d), "l"(ad), "l"(bd), "r"(idesc), "r"(z), "r"(en)
        : "memory");
}

#define MBAR_INIT(a, cnt) \
    asm volatile("mbarrier.init.shared.b64 [%0], %1;" :: "r"(a), "r"(cnt) : "memory")

#define MBAR_WAIT(a, ph) do {                                                  \
    uint32_t _m = (a), _p = (ph), _done;                                       \
    asm volatile(                                                              \
        "{\n\t.reg .pred p;\n\t"                                               \
        "mbarrier.try_wait.parity.acquire.cta.shared::cta.b64 p, [%1], %2;\n\t"\
        "selp.b32 %0, 1, 0, p;\n\t}"                                           \
        : "=r"(_done) : "r"(_m), "r"(_p) : "memory");                          \
    if (!_done) {                                                              \
        asm volatile(                                                          \
            "{\n\t.reg .pred P1;\n\t"                                          \
            "W_%=:\n\t"                                                        \
            "mbarrier.try_wait.parity.acquire.cta.shared::cta.b64 P1, [%0], %1, 0x989680;\n\t" \
            "@P1 bra.uni D_%=;\n\t"                                            \
            "bra.uni W_%=;\n\t"                                                \
            "D_%=:\n\t}"                                                       \
            :: "r"(_m), "r"(_p) : "memory");                                   \
    }                                                                          \
} while (0)

#define LDTM_X32(r, a)                                                         \
    asm volatile(                                                              \
        "tcgen05.ld.sync.aligned.32x32b.x32.b32 "                              \
        "{%0, %1, %2, %3, %4, %5, %6, %7, "                                    \
        " %8, %9, %10, %11, %12, %13, %14, %15, "                              \
        " %16, %17, %18, %19, %20, %21, %22, %23, "                            \
        " %24, %25, %26, %27, %28, %29, %30, %31}, [%32];"                     \
        : "=r"((r)[0]),  "=r"((r)[1]),  "=r"((r)[2]),  "=r"((r)[3]),           \
          "=r"((r)[4]),  "=r"((r)[5]),  "=r"((r)[6]),  "=r"((r)[7]),           \
          "=r"((r)[8]),  "=r"((r)[9]),  "=r"((r)[10]), "=r"((r)[11]),          \
          "=r"((r)[12]), "=r"((r)[13]), "=r"((r)[14]), "=r"((r)[15]),          \
          "=r"((r)[16]), "=r"((r)[17]), "=r"((r)[18]), "=r"((r)[19]),          \
          "=r"((r)[20]), "=r"((r)[21]), "=r"((r)[22]), "=r"((r)[23]),          \
          "=r"((r)[24]), "=r"((r)[25]), "=r"((r)[26]), "=r"((r)[27]),          \
          "=r"((r)[28]), "=r"((r)[29]), "=r"((r)[30]), "=r"((r)[31])           \
        : "r"(a))
#else
// fallback: register-fragment TF32 mma.sync
__device__ __forceinline__ void mma_tf32_frag(float* c, const uint32_t* a, const uint32_t* b) {
    asm volatile(
        "mma.sync.aligned.m16n8k8.row.col.f32.tf32.tf32.f32 "
        "{%0,%1,%2,%3}, {%4,%5,%6,%7}, {%8,%9}, {%0,%1,%2,%3};\n"
        : "+f"(c[0]), "+f"(c[1]), "+f"(c[2]), "+f"(c[3])
        : "r"(a[0]), "r"(a[1]), "r"(a[2]), "r"(a[3]), "r"(b[0]), "r"(b[1]));
}
#endif

// ---------------------------------------------------------------------------
// Weight transpose + tf32 rounding: out[n*K + k] = rna(in[k*N + n]), per z-slice
// ---------------------------------------------------------------------------
__global__ void transpose_tf32_kernel(const float* __restrict__ in, float* __restrict__ out,
                                      int K, int N) {
    __shared__ float t[32][33];
    const float* ip = in + (size_t)blockIdx.z * K * N;
    float* op = out + (size_t)blockIdx.z * K * N;
    int k0 = blockIdx.y << 5, n0 = blockIdx.x << 5;
    int tx = threadIdx.x, ty = threadIdx.y;
#pragma unroll
    for (int i = 0; i < 32; i += 8)
        t[ty + i][tx] = ip[(size_t)(k0 + ty + i) * N + n0 + tx];
    __syncthreads();
#pragma unroll
    for (int i = 0; i < 32; i += 8)
        op[(size_t)(n0 + ty + i) * K + k0 + tx] = __uint_as_float(rna_tf32(t[tx][ty + i]));
}

// ---------------------------------------------------------------------------
// TF32 GEMM: C[M,N] = A[M,K] @ Bt[N,K]^T (+bias), epilogues:
//   EPI=0: store   EPI=1: gelu   EPI=2: accumulate into C
// tcgen05 path: tile 128x128, BK=32, double-buffered SW128 smem, TMEM accum.
// fallback path: mma.sync m16n8k8, tile 128x128, BK=16, 8 warps.
// Requires M%128==0, N%128==0, K%32==0. Launch: 256 threads, 66560B dyn smem.
// ---------------------------------------------------------------------------
template <int EPI>
__global__ void __launch_bounds__(256)
tc_gemm(const float* __restrict__ A, const float* __restrict__ Bt,
        const float* __restrict__ bias, float* __restrict__ C,
        int M, int N, int K) {
    extern __shared__ __align__(1024) char smem[];
    int tid = threadIdx.x, wid = tid >> 5, lid = tid & 31;
    size_t row0 = (size_t)blockIdx.y << 7, col0 = (size_t)blockIdx.x << 7;

#if HAS_TCGEN05
    uint32_t sb = smem_u32(smem);
    const uint32_t SM_A = 1024, SM_B = 1024 + 32768;

    if (wid == 0) {
        asm volatile("tcgen05.alloc.cta_group::1.sync.aligned.shared::cta.b32 [%0], %1;"
                     :: "r"(sb), "r"(128u) : "memory");
        asm volatile("tcgen05.relinquish_alloc_permit.cta_group::1.sync.aligned;");
    }
    if (tid == 0) { MBAR_INIT(sb + 8, 1u); MBAR_INIT(sb + 16, 1u); }
    __syncthreads();
    uint32_t tmem = *(volatile uint32_t*)smem;

    // fill mapping: 2 threads per row, 16 k each (4 x float4)
    int fr = tid >> 1;
    int fk = (tid & 1) << 4;
    const float* Ap = A + (row0 + fr) * (size_t)K + fk;
    const float* Bp = Bt + (col0 + fr) * (size_t)K + fk;
    uint32_t so[4];
#pragma unroll
    for (int j = 0; j < 4; j++) {
        uint32_t o = ((uint32_t)(fr >> 3) << 10) | ((uint32_t)(fr & 7) << 7) |
                     ((uint32_t)(fk + 4 * j) << 2);
        so[j] = o ^ ((o >> 3) & 0x70);
    }

    const int nch = K >> 5;
    const uint32_t idesc = 0x8200910u;   // f32 acc, tf32 a/b, N=128, M=128, K-major
    int ph0 = 0, ph1 = 0;

    for (int c = 0; c < nch; c++) {
        int buf = c & 1;
        if (c >= 2) {
            if (buf == 0) { MBAR_WAIT(sb + 8, ph0);  ph0 ^= 1; }
            else          { MBAR_WAIT(sb + 16, ph1); ph1 ^= 1; }
        }
        uint32_t ab = sb + SM_A + ((uint32_t)buf << 14);
        uint32_t bb = sb + SM_B + ((uint32_t)buf << 14);
        const float* ap = Ap + ((size_t)c << 5);
        const float* bp = Bp + ((size_t)c << 5);
#pragma unroll
        for (int j = 0; j < 4; j++) {
            float4 va = *(const float4*)(ap + 4 * j);
            float4 vb = *(const float4*)(bp + 4 * j);
            uint32_t a0 = rna_tf32(va.x), a1 = rna_tf32(va.y),
                     a2 = rna_tf32(va.z), a3 = rna_tf32(va.w);
            uint32_t b0 = rna_tf32(vb.x), b1 = rna_tf32(vb.y),
                     b2 = rna_tf32(vb.z), b3 = rna_tf32(vb.w);
            asm volatile("st.shared.v4.b32 [%0], {%1,%2,%3,%4};"
                         :: "r"(ab + so[j]), "r"(a0), "r"(a1), "r"(a2), "r"(a3));
            asm volatile("st.shared.v4.b32 [%0], {%1,%2,%3,%4};"
                         :: "r"(bb + so[j]), "r"(b0), "r"(b1), "r"(b2), "r"(b3));
        }
        asm volatile("fence.proxy.async.shared::cta;" ::: "memory");
        __syncthreads();
        if (wid == 0) {
            if (elect_one_pred()) {
                uint64_t ad = make_desc_sw128(ab);
                uint64_t bd = make_desc_sw128(bb);
#pragma unroll
                for (int ks = 0; ks < 4; ks++)
                    mma_tf32_ss(tmem, ad + 2 * ks, bd + 2 * ks, idesc,
                                (uint32_t)((c | ks) != 0));
                asm volatile(
                    "tcgen05.commit.cta_group::1.mbarrier::arrive::one.shared::cluster.b64 [%0];"
                    :: "r"(sb + 8 + ((uint32_t)buf << 3)) : "memory");
            }
        }
    }
    if (((nch - 1) & 1) == 0) { MBAR_WAIT(sb + 8, ph0); }
    else                      { MBAR_WAIT(sb + 16, ph1); }
    asm volatile("tcgen05.fence::after_thread_sync;" ::: "memory");

    // epilogue: warps 0-3 cols [0,64), warps 4-7 cols [64,128); warp reads its
    // own 32-lane subpartition (rows = (wid&3)*32 + lid), 2 chunks of 32 cols.
    int sub = wid & 3, half = wid >> 2;
    size_t grow = row0 + sub * 32 + lid;
#pragma unroll
    for (int cc = 0; cc < 2; cc++) {
        int nc0 = half * 64 + cc * 32;
        uint32_t d[32];
        LDTM_X32(d, tmem + (uint32_t)nc0);
        asm volatile("tcgen05.wait::ld.sync.aligned;" ::: "memory");
#pragma unroll
        for (int j = 0; j < 32; j += 4) {
            size_t col = col0 + nc0 + j;
            float v0 = __uint_as_float(d[j + 0]) + (bias ? bias[col + 0] : 0.f);
            float v1 = __uint_as_float(d[j + 1]) + (bias ? bias[col + 1] : 0.f);
            float v2 = __uint_as_float(d[j + 2]) + (bias ? bias[col + 2] : 0.f);
            float v3 = __uint_as_float(d[j + 3]) + (bias ? bias[col + 3] : 0.f);
            float* cp = &C[grow * (size_t)N + col];
            if (EPI == 1) { v0 = gelu_f(v0); v1 = gelu_f(v1); v2 = gelu_f(v2); v3 = gelu_f(v3); }
            if (EPI == 2) { float4 o = *(const float4*)cp; v0 += o.x; v1 += o.y; v2 += o.z; v3 += o.w; }
            float4 r; r.x = v0; r.y = v1; r.z = v2; r.w = v3;
            *(float4*)cp = r;
        }
    }
    __syncthreads();
    if (wid == 0) {
        asm volatile("tcgen05.dealloc.cta_group::1.sync.aligned.b32 %0, %1;"
                     :: "r"(tmem), "r"(128u));
    }
#else
    // ---------------- fallback: mma.sync TF32, BK=16, symmetric tiles -------
    float* As = (float*)smem;                 // [128][20] : As[m][k]
    float* Bs = (float*)(smem + 10240);       // [128][20] : Bs[n][k]

    const int wm = (wid & 3) << 5;
    const int wn = (wid >> 2) << 6;
    const int g  = lid >> 2;
    const int cq = lid & 3;

    const int fr = tid >> 1;                  // 0..127
    const int fk = (tid & 1) << 3;            // 0 or 8
    const float* Ap = A + (row0 + fr) * (size_t)K + fk;
    const float* Bp = Bt + (col0 + fr) * (size_t)K + fk;

    float acc[2][8][4];
#pragma unroll
    for (int i = 0; i < 2; i++)
#pragma unroll
        for (int j = 0; j < 8; j++)
#pragma unroll
            for (int k = 0; k < 4; k++) acc[i][j][k] = 0.f;

    for (int k0 = 0; k0 < K; k0 += 16) {
        float4 a0 = *(const float4*)(Ap + k0);
        float4 a1 = *(const float4*)(Ap + k0 + 4);
        float4 b0 = *(const float4*)(Bp + k0);
        float4 b1 = *(const float4*)(Bp + k0 + 4);
        *(float4*)&As[fr * 20 + fk]     = a0;
        *(float4*)&As[fr * 20 + fk + 4] = a1;
        *(float4*)&Bs[fr * 20 + fk]     = b0;
        *(float4*)&Bs[fr * 20 + fk + 4] = b1;
        __syncthreads();
#pragma unroll
        for (int ks = 0; ks < 16; ks += 8) {
            uint32_t af[2][4];
#pragma unroll
            for (int mt = 0; mt < 2; mt++) {
                int m = wm + (mt << 4);
                af[mt][0] = rna_tf32(As[(m + g) * 20 + ks + cq]);
                af[mt][1] = rna_tf32(As[(m + g + 8) * 20 + ks + cq]);
                af[mt][2] = rna_tf32(As[(m + g) * 20 + ks + cq + 4]);
                af[mt][3] = rna_tf32(As[(m + g + 8) * 20 + ks + cq + 4]);
            }
#pragma unroll
            for (int nt = 0; nt < 8; nt++) {
                uint32_t bf[2];
                bf[0] = rna_tf32(Bs[(wn + (nt << 3) + g) * 20 + ks + cq]);
                bf[1] = rna_tf32(Bs[(wn + (nt << 3) + g) * 20 + ks + cq + 4]);
                mma_tf32_frag(acc[0][nt], af[0], bf);
                mma_tf32_frag(acc[1][nt], af[1], bf);
            }
        }
        __syncthreads();
    }

#pragma unroll
    for (int mt = 0; mt < 2; mt++) {
        size_t r_hi = row0 + wm + (mt << 4) + g;
#pragma unroll
        for (int nt = 0; nt < 8; nt++) {
            size_t cb = col0 + wn + (nt << 3) + (cq << 1);
            float bv0 = bias ? bias[cb] : 0.f;
            float bv1 = bias ? bias[cb + 1] : 0.f;
#pragma unroll
            for (int rr = 0; rr < 2; rr++) {
                size_t r = r_hi + rr * 8;
                float v0 = acc[mt][nt][rr * 2 + 0] + bv0;
                float v1 = acc[mt][nt][rr * 2 + 1] + bv1;
                float* cp = &C[r * (size_t)N + cb];
                if (EPI == 1) { v0 = gelu_f(v0); v1 = gelu_f(v1); }
                if (EPI == 2) { v0 += cp[0]; v1 += cp[1]; }
                cp[0] = v0;
                cp[1] = v1;
            }
        }
    }
#endif
}

// ---------------------------------------------------------------------------
// Embedding
// ---------------------------------------------------------------------------
__global__ void embed_kernel(const int* __restrict__ idxs,
                             const float* __restrict__ lat,
                             const float* __restrict__ lon,
                             const float* __restrict__ sog,
                             const float* __restrict__ cog,
                             const float* __restrict__ pos) {
    int row = blockIdx.x;
    int tid = threadIdx.x;
    int t = row & (SEQ - 1);
#pragma unroll
    for (int e = 0; e < 3; e++) {
        int j = (e << 8) + tid;
        int seg = j / 192;
        int off = j - seg * 192;
        int id = idxs[row * 4 + seg];
        const float* tab = (seg == 0) ? lat : (seg == 1) ? lon : (seg == 2) ? sog : cog;
        g_h[(size_t)row * DMODEL + j] = tab[id * 192 + off] + pos[t * DMODEL + j];
    }
}

// ---------------------------------------------------------------------------
// LayerNorm: one block per row.
// ---------------------------------------------------------------------------
__global__ void ln_kernel(const float* __restrict__ in, float* __restrict__ out,
                          const float* __restrict__ gamma, const float* __restrict__ beta) {
    int row = blockIdx.x;
    int tid = threadIdx.x;
    const float* x = in + (size_t)row * DMODEL;
    float v0 = x[tid], v1 = x[tid + 256], v2 = x[tid + 512];

    __shared__ float red[8];
    __shared__ float s_mean, s_rstd;

    float s = v0 + v1 + v2;
#pragma unroll
    for (int o = 16; o; o >>= 1) s += __shfl_xor_sync(0xffffffffu, s, o);
    if ((tid & 31) == 0) red[tid >> 5] = s;
    __syncthreads();
    if (tid == 0) {
        float t = 0.f;
#pragma unroll
        for (int i = 0; i < 8; i++) t += red[i];
        s_mean = t * (1.0f / 768.0f);
    }
    __syncthreads();
    float m = s_mean;
    float d0 = v0 - m, d1 = v1 - m, d2 = v2 - m;
    float q = d0 * d0 + d1 * d1 + d2 * d2;
#pragma unroll
    for (int o = 16; o; o >>= 1) q += __shfl_xor_sync(0xffffffffu, q, o);
    if ((tid & 31) == 0) red[tid >> 5] = q;
    __syncthreads();
    if (tid == 0) {
        float t = 0.f;
#pragma unroll
        for (int i = 0; i < 8; i++) t += red[i];
        s_rstd = rsqrtf(t * (1.0f / 768.0f) + 1e-5f);
    }
    __syncthreads();
    float r = s_rstd;
    float* o_ = out + (size_t)row * DMODEL;
    o_[tid]       = d0 * r * gamma[tid]       + beta[tid];
    o_[tid + 256] = d1 * r * gamma[tid + 256] + beta[tid + 256];
    o_[tid + 512] = d2 * r * gamma[tid + 512] + beta[tid + 512];
}

// ---------------------------------------------------------------------------
// SIMT SGEMM for the head (N=302)
// ---------------------------------------------------------------------------
__global__ void sgemm_head_kernel(const float* __restrict__ A, const float* __restrict__ B,
                                  float* __restrict__ C, int M, int N, int K) {
    __shared__ float As[16][65];
    __shared__ float Bs[16][64];
    int tid = threadIdx.x;
    int tx = tid & 15, ty = tid >> 4;
    int row0 = blockIdx.y << 6, col0 = blockIdx.x << 6;
    float acc[4][4] = {};

    for (int k0 = 0; k0 < K; k0 += 16) {
#pragma unroll
        for (int i = tid; i < 1024; i += 256) {
            int r = i >> 4, c = i & 15;
            As[c][r] = A[(size_t)(row0 + r) * K + (k0 + c)];
        }
#pragma unroll
        for (int i = tid; i < 1024; i += 256) {
            int r = i >> 6, c = i & 63;
            int col = col0 + c;
            Bs[r][c] = (col < N) ? B[(size_t)(k0 + r) * N + col] : 0.f;
        }
        __syncthreads();
#pragma unroll
        for (int kk = 0; kk < 16; kk++) {
            float a[4], b[4];
#pragma unroll
            for (int i = 0; i < 4; i++) a[i] = As[kk][ty * 4 + i];
#pragma unroll
            for (int j = 0; j < 4; j++) b[j] = Bs[kk][tx * 4 + j];
#pragma unroll
            for (int i = 0; i < 4; i++)
#pragma unroll
                for (int j = 0; j < 4; j++) acc[i][j] += a[i] * b[j];
        }
        __syncthreads();
    }

#pragma unroll
    for (int i = 0; i < 4; i++) {
        int r = row0 + ty * 4 + i;
#pragma unroll
        for (int j = 0; j < 4; j++) {
            int col = col0 + tx * 4 + j;
            if (col < N) C[(size_t)r * N + col] = acc[i][j];
        }
    }
}

// ---------------------------------------------------------------------------
// QK^T (SIMT, causal tiles only)
// ---------------------------------------------------------------------------
__global__ void qk_kernel(const float* __restrict__ Q, const float* __restrict__ K,
                          float* __restrict__ S) {
    int tq = blockIdx.x >> 2, tk = blockIdx.x & 3;
    if (tk > tq) return;
    int bh = blockIdx.y;
    int b = bh / NHEAD, h = bh % NHEAD;
    const float* Qp = Q + (size_t)b * SEQ * DMODEL + h * HDIM;
    const float* Kp = K + (size_t)b * SEQ * DMODEL + h * HDIM;
    float* Sp = S + (size_t)bh * (SEQ * SEQ);

    __shared__ float As[16][65];
    __shared__ float Bs[16][65];
    int tid = threadIdx.x;
    int tx = tid & 15, ty = tid >> 4;
    int row0 = tq << 6, col0 = tk << 6;
    float acc[4][4] = {};

    for (int k0 = 0; k0 < HDIM; k0 += 16) {
#pragma unroll
        for (int i = tid; i < 1024; i += 256) {
            int r = i >> 4, c = i & 15;
            As[c][r] = Qp[(size_t)(row0 + r) * DMODEL + (k0 + c)];
        }
#pragma unroll
        for (int i = tid; i < 1024; i += 256) {
            int r = i & 15, c = i >> 4;
            Bs[r][c] = Kp[(size_t)(col0 + c) * DMODEL + (k0 + r)];
        }
        __syncthreads();
#pragma unroll
        for (int kk = 0; kk < 16; kk++) {
            float a[4], bb[4];
#pragma unroll
            for (int i = 0; i < 4; i++) a[i] = As[kk][ty * 4 + i];
#pragma unroll
            for (int j = 0; j < 4; j++) bb[j] = Bs[kk][tx * 4 + j];
#pragma unroll
            for (int i = 0; i < 4; i++)
#pragma unroll
                for (int j = 0; j < 4; j++) acc[i][j] += a[i] * bb[j];
        }
        __syncthreads();
    }

#pragma unroll
    for (int i = 0; i < 4; i++)
#pragma unroll
        for (int j = 0; j < 4; j++)
            Sp[(size_t)(row0 + ty * 4 + i) * SEQ + (col0 + tx * 4 + j)] = acc[i][j] * 0.125f;
}

// ---------------------------------------------------------------------------
// Causal softmax in place
// ---------------------------------------------------------------------------
__global__ void softmax_kernel(float* __restrict__ S) {
    int w = (blockIdx.x << 3) + (threadIdx.x >> 5);
    int q = w & (SEQ - 1);
    float* row = S + (size_t)(w >> 8) * (SEQ * SEQ) + (size_t)q * SEQ;
    int lane = threadIdx.x & 31;

    float v[8];
    float mx = -1e30f;
#pragma unroll
    for (int kk = 0; kk < 8; kk++) {
        int k = (kk << 5) + lane;
        float s = (k <= q) ? row[k] : -1e30f;
        v[kk] = s;
        mx = fmaxf(mx, s);
    }
#pragma unroll
    for (int o = 16; o; o >>= 1) mx = fmaxf(mx, __shfl_xor_sync(0xffffffffu, mx, o));
    float sum = 0.f;
#pragma unroll
    for (int kk = 0; kk < 8; kk++) {
        float e = expf(v[kk] - mx);
        v[kk] = e;
        sum += e;
    }
#pragma unroll
    for (int o = 16; o; o >>= 1) sum += __shfl_xor_sync(0xffffffffu, sum, o);
    float inv = 1.0f / sum;
#pragma unroll
    for (int kk = 0; kk < 8; kk++) {
        int k = (kk << 5) + lane;
        row[k] = v[kk] * inv;
    }
}

// ---------------------------------------------------------------------------
// AV (SIMT, causal k-truncation)
// ---------------------------------------------------------------------------
__global__ void av_kernel(const float* __restrict__ S, const float* __restrict__ V,
                          float* __restrict__ Y) {
    int bh = blockIdx.y;
    int b = bh / NHEAD, h = bh % NHEAD;
    const float* Sp = S + (size_t)bh * (SEQ * SEQ);
    const float* Vp = V + (size_t)b * SEQ * DMODEL + h * HDIM;
    float* Yp = Y + (size_t)b * SEQ * DMODEL + h * HDIM;

    __shared__ float As[16][65];
    __shared__ float Bs[16][64];
    int tid = threadIdx.x;
    int tx = tid & 15, ty = tid >> 4;
    int row0 = blockIdx.x << 6;
    int kend = row0 + 64;
    float acc[4][4] = {};

    for (int k0 = 0; k0 < kend; k0 += 16) {
#pragma unroll
        for (int i = tid; i < 1024; i += 256) {
            int r = i >> 4, c = i & 15;
            As[c][r] = Sp[(size_t)(row0 + r) * SEQ + (k0 + c)];
        }
#pragma unroll
        for (int i = tid; i < 1024; i += 256) {
            int r = i >> 6, c = i & 63;
            Bs[r][c] = Vp[(size_t)(k0 + r) * DMODEL + c];
        }
        __syncthreads();
#pragma unroll
        for (int kk = 0; kk < 16; kk++) {
            float a[4], bb[4];
#pragma unroll
            for (int i = 0; i < 4; i++) a[i] = As[kk][ty * 4 + i];
#pragma unroll
            for (int j = 0; j < 4; j++) bb[j] = Bs[kk][tx * 4 + j];
#pragma unroll
            for (int i = 0; i < 4; i++)
#pragma unroll
                for (int j = 0; j < 4; j++) acc[i][j] += a[i] * bb[j];
        }
        __syncthreads();
    }

#pragma unroll
    for (int i = 0; i < 4; i++)
#pragma unroll
        for (int j = 0; j < 4; j++)
            Yp[(size_t)(row0 + ty * 4 + i) * DMODEL + (tx * 4 + j)] = acc[i][j];
}

// ---------------------------------------------------------------------------
// Launch
// ---------------------------------------------------------------------------
extern "C" void kernel_launch(void* const* d_in, const int* in_sizes, int n_in,
                              void* d_out, int out_size) {
    const int*   idxs  = (const int*)  d_in[0];
    const float* lat   = (const float*)d_in[1];
    const float* lon   = (const float*)d_in[2];
    const float* sog   = (const float*)d_in[3];
    const float* cog   = (const float*)d_in[4];
    const float* pos   = (const float*)d_in[5];
    const float* ln1_g = (const float*)d_in[6];
    const float* ln1_b = (const float*)d_in[7];
    const float* ln2_g = (const float*)d_in[8];
    const float* ln2_b = (const float*)d_in[9];
    const float* Wq    = (const float*)d_in[10];
    const float* bq    = (const float*)d_in[11];
    const float* Wk    = (const float*)d_in[12];
    const float* bk    = (const float*)d_in[13];
    const float* Wv    = (const float*)d_in[14];
    const float* bv    = (const float*)d_in[15];
    const float* Wo    = (const float*)d_in[16];
    const float* bo    = (const float*)d_in[17];
    const float* W1    = (const float*)d_in[18];
    const float* b1    = (const float*)d_in[19];
    const float* W2    = (const float*)d_in[20];
    const float* b2    = (const float*)d_in[21];
    const float* lnf_g = (const float*)d_in[22];
    const float* lnf_b = (const float*)d_in[23];
    const float* Whead = (const float*)d_in[24];
    float* out = (float*)d_out;

    float *hb, *xb, *qb, *kb, *vb, *yb, *sb, *wt;
    cudaGetSymbolAddress((void**)&hb, g_h);
    cudaGetSymbolAddress((void**)&xb, g_x);
    cudaGetSymbolAddress((void**)&qb, g_q);
    cudaGetSymbolAddress((void**)&kb, g_k);
    cudaGetSymbolAddress((void**)&vb, g_v);
    cudaGetSymbolAddress((void**)&yb, g_y);
    cudaGetSymbolAddress((void**)&sb, g_s);
    cudaGetSymbolAddress((void**)&wt, g_wt);

    const size_t DD = (size_t)DMODEL * DMODEL;     // 589824
    const size_t DF = (size_t)DMODEL * DFF;        // 2359296
    const size_t DD12 = DD * NLAYER;               // 7077888
    float* Wq_t = wt;
    float* Wk_t = wt + DD12;
    float* Wv_t = wt + 2 * DD12;
    float* Wo_t = wt + 3 * DD12;
    float* W1_t = wt + 4 * DD12;                   // [12][3072][768]
    float* W2_t = wt + 4 * DD12 + DF * NLAYER;     // [12][768][3072]

    const int GEMM_SMEM = 1024 + 65536;
    cudaFuncSetAttribute(tc_gemm<0>, cudaFuncAttributeMaxDynamicSharedMemorySize, GEMM_SMEM);
    cudaFuncSetAttribute(tc_gemm<1>, cudaFuncAttributeMaxDynamicSharedMemorySize, GEMM_SMEM);
    cudaFuncSetAttribute(tc_gemm<2>, cudaFuncAttributeMaxDynamicSharedMemorySize, GEMM_SMEM);

    // weight transposes (per replay; ~140us)
    {
        dim3 blk(32, 8);
        dim3 gdd(DMODEL / 32, DMODEL / 32, NLAYER);
        transpose_tf32_kernel<<<gdd, blk>>>(Wq, Wq_t, DMODEL, DMODEL);
        transpose_tf32_kernel<<<gdd, blk>>>(Wk, Wk_t, DMODEL, DMODEL);
        transpose_tf32_kernel<<<gdd, blk>>>(Wv, Wv_t, DMODEL, DMODEL);
        transpose_tf32_kernel<<<gdd, blk>>>(Wo, Wo_t, DMODEL, DMODEL);
        dim3 g1(DFF / 32, DMODEL / 32, NLAYER);
        transpose_tf32_kernel<<<g1, blk>>>(W1, W1_t, DMODEL, DFF);
        dim3 g2(DMODEL / 32, DFF / 32, NLAYER);
        transpose_tf32_kernel<<<g2, blk>>>(W2, W2_t, DFF, DMODEL);
    }

    embed_kernel<<<M_ROWS, 256>>>(idxs, lat, lon, sog, cog, pos);

    dim3 gD(DMODEL / 128, M_ROWS / 128);     // (6, 128)
    dim3 gF(DFF / 128, M_ROWS / 128);        // (24, 128)
    dim3 gQK(16, NHEAD * 64);
    dim3 gAV(4, NHEAD * 64);
    dim3 gHead((NOUT + 63) / 64, M_ROWS / 64);

    for (int l = 0; l < NLAYER; l++) {
        ln_kernel<<<M_ROWS, 256>>>(hb, xb, ln1_g + l * DMODEL, ln1_b + l * DMODEL);
        tc_gemm<0><<<gD, 256, GEMM_SMEM>>>(xb, Wq_t + l * DD, bq + l * DMODEL, qb, M_ROWS, DMODEL, DMODEL);
        tc_gemm<0><<<gD, 256, GEMM_SMEM>>>(xb, Wk_t + l * DD, bk + l * DMODEL, kb, M_ROWS, DMODEL, DMODEL);
        tc_gemm<0><<<gD, 256, GEMM_SMEM>>>(xb, Wv_t + l * DD, bv + l * DMODEL, vb, M_ROWS, DMODEL, DMODEL);
        qk_kernel<<<gQK, 256>>>(qb, kb, sb);
        softmax_kernel<<<(NHEAD * 64 * SEQ) / 8, 256>>>(sb);
        av_kernel<<<gAV, 256>>>(sb, vb, yb);
        tc_gemm<2><<<gD, 256, GEMM_SMEM>>>(yb, Wo_t + l * DD, bo + l * DMODEL, hb, M_ROWS, DMODEL, DMODEL);
        ln_kernel<<<M_ROWS, 256>>>(hb, xb, ln2_g + l * DMODEL, ln2_b + l * DMODEL);
        tc_gemm<1><<<gF, 256, GEMM_SMEM>>>(xb, W1_t + l * DF, b1 + l * DFF, sb, M_ROWS, DFF, DMODEL);
        tc_gemm<2><<<gD, 256, GEMM_SMEM>>>(sb, W2_t + l * DF, b2 + l * DMODEL, hb, M_ROWS, DMODEL, DFF);
    }

    ln_kernel<<<M_ROWS, 256>>>(hb, xb, lnf_g, lnf_b);
    sgemm_head_kernel<<<gHead, 256>>>(xb, Whead, out, M_ROWS, NOUT, DMODEL);
}

// round 5
// speedup vs baseline: 1.6197x; 1.6197x over previous
#include <cuda_runtime.h>
#include <math.h>
#include <stdint.h>

// ---------------------------------------------------------------------------
// TrAISformer forward. Big GEMMs on tcgen05 (tf32, SS mode, TMEM accum) when
// compiled for sm_103a/f; mma.sync TF32 fallback for the featureless pass.
// Activations are tf32-rounded at producers so the GEMM fill has zero cvt.
// B=64, T=256, D=768, H=12, HD=64, L=12, FFN=3072, OUT=302. M = B*T = 16384.
// ---------------------------------------------------------------------------

#if defined(__CUDA_ARCH__) && (defined(__CUDA_ARCH_FEAT_SM103_ALL) || \
    (defined(__CUDA_ARCH_SPECIFIC__) && (__CUDA_ARCH_SPECIFIC__ == 1030)) || \
    (defined(__CUDA_ARCH_FAMILY_SPECIFIC__) && (__CUDA_ARCH_FAMILY_SPECIFIC__ == 1030)))
#define HAS_TCGEN05 1
#else
#define HAS_TCGEN05 0
#endif

#define M_ROWS   16384
#define DMODEL   768
#define NHEAD    12
#define HDIM     64
#define NLAYER   12
#define DFF      3072
#define NOUT     302
#define SEQ      256

__device__ float g_h[M_ROWS * DMODEL];
__device__ float g_x[M_ROWS * DMODEL];
__device__ float g_q[M_ROWS * DMODEL];
__device__ float g_k[M_ROWS * DMODEL];
__device__ float g_v[M_ROWS * DMODEL];
__device__ float g_y[M_ROWS * DMODEL];
__device__ float g_s[50331648];
// transposed (K-major, tf32-rounded) weights: Wq,Wk,Wv,Wo (4 x 12 x 768x768),
// then W1 (12 x 3072x768), then W2 (12 x 768x3072)
__device__ float g_wt[84934656];

__device__ __forceinline__ float gelu_f(float v) {
    return 0.5f * v * (1.0f + erff(v * 0.70710678118654752f));
}

__device__ __forceinline__ uint32_t rna_tf32(float x) {
    uint32_t u;
    asm("cvt.rna.tf32.f32 %0, %1;" : "=r"(u) : "f"(x));
    return u;
}

__device__ __forceinline__ float rna_tf32_f(float x) {
    return __uint_as_float(rna_tf32(x));
}

__device__ __forceinline__ uint32_t smem_u32(const void* p) {
    uint32_t a;
    asm("{ .reg .u64 t; cvta.to.shared.u64 t, %1; cvt.u32.u64 %0, t; }" : "=r"(a) : "l"(p));
    return a;
}

#if HAS_TCGEN05
__device__ __forceinline__ uint32_t elect_one_pred() {
    uint32_t pred;
    asm volatile(
        "{\n\t.reg .pred p;\n\telect.sync _|p, 0xFFFFFFFF;\n\tselp.b32 %0, 1, 0, p;\n\t}"
        : "=r"(pred));
    return pred;
}

__device__ __forceinline__ uint64_t make_desc_sw128(uint32_t addr) {
    const uint64_t base = (uint64_t(2) << 61) | (uint64_t(1) << 46) |
                          (uint64_t(64) << 32) | (uint64_t(1) << 16);
    return base | ((addr >> 4) & 0x3FFF);
}

__device__ __forceinline__ void mma_tf32_ss(uint32_t d, uint64_t ad, uint64_t bd,
                                            uint32_t idesc, uint32_t en) {
    uint32_t z = 0;
    asm volatile(
        "{\n\t"
        ".reg .pred p;\n\t"
        "setp.ne.u32 p, %5, 0;\n\t"
        "tcgen05.mma.cta_group::1.kind::tf32 [%0], %1, %2, %3, {%4, %4, %4, %4}, p;\n\t"
        "}"
        :: "r"(d), "l"(ad), "l"(bd), "r"(idesc), "r"(z), "r"(en)
        : "memory");
}

#define MBAR_INIT(a, cnt) \
    asm volatile("mbarrier.init.shared.b64 [%0], %1;" :: "r"(a), "r"(cnt) : "memory")

#define MBAR_WAIT(a, ph) do {                                                  \
    uint32_t _m = (a), _p = (ph), _done;                                       \
    asm volatile(                                                              \
        "{\n\t.reg .pred p;\n\t"                                               \
        "mbarrier.try_wait.parity.acquire.cta.shared::cta.b64 p, [%1], %2;\n\t"\
        "selp.b32 %0, 1, 0, p;\n\t}"                                           \
        : "=r"(_done) : "r"(_m), "r"(_p) : "memory");                          \
    if (!_done) {                                                              \
        asm volatile(                                                          \
            "{\n\t.reg .pred P1;\n\t"                                          \
            "W_%=:\n\t"                                                        \
            "mbarrier.try_wait.parity.acquire.cta.shared::cta.b64 P1, [%0], %1, 0x989680;\n\t" \
            "@P1 bra.uni D_%=;\n\t"                                            \
            "bra.uni W_%=;\n\t"                                                \
            "D_%=:\n\t}"                                                       \
            :: "r"(_m), "r"(_p) : "memory");                                   \
    }                                                                          \
} while (0)

#define LDTM_X32(r, a)                                                         \
    asm volatile(                                                              \
        "tcgen05.ld.sync.aligned.32x32b.x32.b32 "                              \
        "{%0, %1, %2, %3, %4, %5, %6, %7, "                                    \
        " %8, %9, %10, %11, %12, %13, %14, %15, "                              \
        " %16, %17, %18, %19, %20, %21, %22, %23, "                            \
        " %24, %25, %26, %27, %28, %29, %30, %31}, [%32];"                     \
        : "=r"((r)[0]),  "=r"((r)[1]),  "=r"((r)[2]),  "=r"((r)[3]),           \
          "=r"((r)[4]),  "=r"((r)[5]),  "=r"((r)[6]),  "=r"((r)[7]),           \
          "=r"((r)[8]),  "=r"((r)[9]),  "=r"((r)[10]), "=r"((r)[11]),          \
          "=r"((r)[12]), "=r"((r)[13]), "=r"((r)[14]), "=r"((r)[15]),          \
          "=r"((r)[16]), "=r"((r)[17]), "=r"((r)[18]), "=r"((r)[19]),          \
          "=r"((r)[20]), "=r"((r)[21]), "=r"((r)[22]), "=r"((r)[23]),          \
          "=r"((r)[24]), "=r"((r)[25]), "=r"((r)[26]), "=r"((r)[27]),          \
          "=r"((r)[28]), "=r"((r)[29]), "=r"((r)[30]), "=r"((r)[31])           \
        : "r"(a))
#else
// fallback: register-fragment TF32 mma.sync
__device__ __forceinline__ void mma_tf32_frag(float* c, const uint32_t* a, const uint32_t* b) {
    asm volatile(
        "mma.sync.aligned.m16n8k8.row.col.f32.tf32.tf32.f32 "
        "{%0,%1,%2,%3}, {%4,%5,%6,%7}, {%8,%9}, {%0,%1,%2,%3};\n"
        : "+f"(c[0]), "+f"(c[1]), "+f"(c[2]), "+f"(c[3])
        : "r"(a[0]), "r"(a[1]), "r"(a[2]), "r"(a[3]), "r"(b[0]), "r"(b[1]));
}
#endif

// ---------------------------------------------------------------------------
// One-launch weight transpose + tf32 rounding into g_wt.
// z in [0,48): Wq/Wk/Wv/Wo (768x768, layer z%12); [48,60): W1 (768->3072);
// [60,72): W2 (3072->768, roles of x/y swapped).
// ---------------------------------------------------------------------------
__global__ void transpose_all_kernel(const float* __restrict__ Wq,
                                     const float* __restrict__ Wk,
                                     const float* __restrict__ Wv,
                                     const float* __restrict__ Wo,
                                     const float* __restrict__ W1,
                                     const float* __restrict__ W2,
                                     float* __restrict__ wt) {
    const size_t DD = (size_t)DMODEL * DMODEL;
    const size_t DF = (size_t)DMODEL * DFF;
    const size_t DD12 = DD * NLAYER;

    int z = blockIdx.z;
    const float* src;
    float* dst;
    int K, N, ktile, ntile;
    if (z < 48) {
        int grp = z / 12, l = z % 12;
        const float* bases[4] = {Wq, Wk, Wv, Wo};
        src = bases[grp] + (size_t)l * DD;
        dst = wt + (size_t)grp * DD12 + (size_t)l * DD;
        K = DMODEL; N = DMODEL;
        ntile = blockIdx.x;
        ktile = blockIdx.y;
        if (ntile >= 24) return;
    } else if (z < 60) {
        int l = z - 48;
        src = W1 + (size_t)l * DF;
        dst = wt + 4 * DD12 + (size_t)l * DF;
        K = DMODEL; N = DFF;
        ntile = blockIdx.x;   // 0..95
        ktile = blockIdx.y;   // 0..23
    } else {
        int l = z - 60;
        src = W2 + (size_t)l * DF;
        dst = wt + 4 * DD12 + (size_t)NLAYER * DF + (size_t)l * DF;
        K = DFF; N = DMODEL;
        ktile = blockIdx.x;   // 0..95
        ntile = blockIdx.y;   // 0..23
    }

    __shared__ float t[32][33];
    int k0 = ktile << 5, n0 = ntile << 5;
    int tx = threadIdx.x, ty = threadIdx.y;
#pragma unroll
    for (int i = 0; i < 32; i += 8)
        t[ty + i][tx] = src[(size_t)(k0 + ty + i) * N + n0 + tx];
    __syncthreads();
#pragma unroll
    for (int i = 0; i < 32; i += 8)
        dst[(size_t)(n0 + ty + i) * K + k0 + tx] = rna_tf32_f(t[tx][ty + i]);
}

// ---------------------------------------------------------------------------
// TF32 GEMM: C[M,N] = A[M,K] @ Bt[N,K]^T (+bias), epilogues:
//   EPI=0: store   EPI=1: gelu (tf32-rounded)   EPI=2: accumulate into C
// A and Bt must already be tf32-rounded (no cvt in this kernel's hot loop).
// tcgen05 path: tile 128x128, BK=32, double-buffered SW128 smem, TMEM accum,
// register prefetch of the next chunk. 512 threads.
// fallback path: mma.sync m16n8k8 on 16 warps.
// Requires M%128==0, N%128==0, K%32==0. Launch: 512 threads, 66560B dyn smem.
// ---------------------------------------------------------------------------
template <int EPI>
__global__ void __launch_bounds__(512)
tc_gemm(const float* __restrict__ A, const float* __restrict__ Bt,
        const float* __restrict__ bias, float* __restrict__ C,
        int M, int N, int K) {
    extern __shared__ __align__(1024) char smem[];
    int tid = threadIdx.x, wid = tid >> 5, lid = tid & 31;
    size_t row0 = (size_t)blockIdx.y << 7, col0 = (size_t)blockIdx.x << 7;

#if HAS_TCGEN05
    uint32_t sb = smem_u32(smem);
    const uint32_t SM_A = 1024, SM_B = 1024 + 32768;

    if (wid == 0) {
        asm volatile("tcgen05.alloc.cta_group::1.sync.aligned.shared::cta.b32 [%0], %1;"
                     :: "r"(sb), "r"(128u) : "memory");
        asm volatile("tcgen05.relinquish_alloc_permit.cta_group::1.sync.aligned;");
    }
    if (tid == 0) { MBAR_INIT(sb + 8, 1u); MBAR_INIT(sb + 16, 1u); }
    __syncthreads();
    uint32_t tmem = *(volatile uint32_t*)smem;

    // fill mapping: 4 threads per row, 8 k each (2 x float4) per matrix
    int fr = tid >> 2;                 // 0..127
    int fk = (tid & 3) << 3;           // 0,8,16,24
    const float* Ap = A + (row0 + fr) * (size_t)K + fk;
    const float* Bp = Bt + (col0 + fr) * (size_t)K + fk;
    uint32_t so[2];
#pragma unroll
    for (int j = 0; j < 2; j++) {
        uint32_t o = ((uint32_t)(fr >> 3) << 10) | ((uint32_t)(fr & 7) << 7) |
                     ((uint32_t)(fk + 4 * j) << 2);
        so[j] = o ^ ((o >> 3) & 0x70);
    }

    const int nch = K >> 5;
    const uint32_t idesc = 0x8200910u;   // f32 acc, tf32 a/b, N=128, M=128, K-major
    int ph0 = 0, ph1 = 0;

    float4 ra[2], rb[2];
#pragma unroll
    for (int j = 0; j < 2; j++) {
        ra[j] = *(const float4*)(Ap + 4 * j);
        rb[j] = *(const float4*)(Bp + 4 * j);
    }

    for (int c = 0; c < nch; c++) {
        int buf = c & 1;
        if (c >= 2) {
            if (buf == 0) { MBAR_WAIT(sb + 8, ph0);  ph0 ^= 1; }
            else          { MBAR_WAIT(sb + 16, ph1); ph1 ^= 1; }
        }
        uint32_t ab = sb + SM_A + ((uint32_t)buf << 14);
        uint32_t bb = sb + SM_B + ((uint32_t)buf << 14);
#pragma unroll
        for (int j = 0; j < 2; j++) {
            asm volatile("st.shared.v4.b32 [%0], {%1,%2,%3,%4};"
                         :: "r"(ab + so[j]),
                            "r"(__float_as_uint(ra[j].x)), "r"(__float_as_uint(ra[j].y)),
                            "r"(__float_as_uint(ra[j].z)), "r"(__float_as_uint(ra[j].w)));
            asm volatile("st.shared.v4.b32 [%0], {%1,%2,%3,%4};"
                         :: "r"(bb + so[j]),
                            "r"(__float_as_uint(rb[j].x)), "r"(__float_as_uint(rb[j].y)),
                            "r"(__float_as_uint(rb[j].z)), "r"(__float_as_uint(rb[j].w)));
        }
        if (c + 1 < nch) {
            const float* ap = Ap + ((size_t)(c + 1) << 5);
            const float* bp = Bp + ((size_t)(c + 1) << 5);
#pragma unroll
            for (int j = 0; j < 2; j++) {
                ra[j] = *(const float4*)(ap + 4 * j);
                rb[j] = *(const float4*)(bp + 4 * j);
            }
        }
        asm volatile("fence.proxy.async.shared::cta;" ::: "memory");
        __syncthreads();
        if (wid == 0) {
            if (elect_one_pred()) {
                uint64_t ad = make_desc_sw128(ab);
                uint64_t bd = make_desc_sw128(bb);
#pragma unroll
                for (int ks = 0; ks < 4; ks++)
                    mma_tf32_ss(tmem, ad + 2 * ks, bd + 2 * ks, idesc,
                                (uint32_t)((c | ks) != 0));
                asm volatile(
                    "tcgen05.commit.cta_group::1.mbarrier::arrive::one.shared::cluster.b64 [%0];"
                    :: "r"(sb + 8 + ((uint32_t)buf << 3)) : "memory");
            }
        }
    }
    if (((nch - 1) & 1) == 0) { MBAR_WAIT(sb + 8, ph0); }
    else                      { MBAR_WAIT(sb + 16, ph1); }
    asm volatile("tcgen05.fence::after_thread_sync;" ::: "memory");

    // epilogue: 16 warps; warp w: rows (w&3)*32 + lane, cols (w>>2)*32..+31
    {
        int sub = wid & 3, cchunk = wid >> 2;
        size_t grow = row0 + sub * 32 + lid;
        int nc0 = cchunk * 32;
        uint32_t d[32];
        LDTM_X32(d, tmem + (uint32_t)nc0);
        asm volatile("tcgen05.wait::ld.sync.aligned;" ::: "memory");
#pragma unroll
        for (int j = 0; j < 32; j += 4) {
            size_t col = col0 + nc0 + j;
            float v0 = __uint_as_float(d[j + 0]) + (bias ? bias[col + 0] : 0.f);
            float v1 = __uint_as_float(d[j + 1]) + (bias ? bias[col + 1] : 0.f);
            float v2 = __uint_as_float(d[j + 2]) + (bias ? bias[col + 2] : 0.f);
            float v3 = __uint_as_float(d[j + 3]) + (bias ? bias[col + 3] : 0.f);
            float* cp = &C[grow * (size_t)N + col];
            if (EPI == 1) {
                v0 = rna_tf32_f(gelu_f(v0)); v1 = rna_tf32_f(gelu_f(v1));
                v2 = rna_tf32_f(gelu_f(v2)); v3 = rna_tf32_f(gelu_f(v3));
            }
            if (EPI == 2) { float4 o = *(const float4*)cp; v0 += o.x; v1 += o.y; v2 += o.z; v3 += o.w; }
            float4 r; r.x = v0; r.y = v1; r.z = v2; r.w = v3;
            *(float4*)cp = r;
        }
    }
    __syncthreads();
    if (wid == 0) {
        asm volatile("tcgen05.dealloc.cta_group::1.sync.aligned.b32 %0, %1;"
                     :: "r"(tmem), "r"(128u));
    }
#else
    // ---------------- fallback: mma.sync TF32, BK=16, 16 warps --------------
    float* As = (float*)smem;                 // [128][20] : As[m][k]
    float* Bs = (float*)(smem + 10240);       // [128][20] : Bs[n][k]

    const int wm = (wid & 3) << 5;
    const int wn = (wid >> 2) << 5;
    const int g  = lid >> 2;
    const int cq = lid & 3;

    const int fr = tid >> 2;                  // 0..127
    const int fk = (tid & 3) << 2;            // 0,4,8,12
    const float* Ap = A + (row0 + fr) * (size_t)K + fk;
    const float* Bp = Bt + (col0 + fr) * (size_t)K + fk;

    float acc[2][4][4];
#pragma unroll
    for (int i = 0; i < 2; i++)
#pragma unroll
        for (int j = 0; j < 4; j++)
#pragma unroll
            for (int k = 0; k < 4; k++) acc[i][j][k] = 0.f;

    for (int k0 = 0; k0 < K; k0 += 16) {
        float4 a0 = *(const float4*)(Ap + k0);
        float4 b0 = *(const float4*)(Bp + k0);
        *(float4*)&As[fr * 20 + fk] = a0;
        *(float4*)&Bs[fr * 20 + fk] = b0;
        __syncthreads();
#pragma unroll
        for (int ks = 0; ks < 16; ks += 8) {
            uint32_t af[2][4];
#pragma unroll
            for (int mt = 0; mt < 2; mt++) {
                int m = wm + (mt << 4);
                af[mt][0] = rna_tf32(As[(m + g) * 20 + ks + cq]);
                af[mt][1] = rna_tf32(As[(m + g + 8) * 20 + ks + cq]);
                af[mt][2] = rna_tf32(As[(m + g) * 20 + ks + cq + 4]);
                af[mt][3] = rna_tf32(As[(m + g + 8) * 20 + ks + cq + 4]);
            }
#pragma unroll
            for (int nt = 0; nt < 4; nt++) {
                uint32_t bf[2];
                bf[0] = rna_tf32(Bs[(wn + (nt << 3) + g) * 20 + ks + cq]);
                bf[1] = rna_tf32(Bs[(wn + (nt << 3) + g) * 20 + ks + cq + 4]);
                mma_tf32_frag(acc[0][nt], af[0], bf);
                mma_tf32_frag(acc[1][nt], af[1], bf);
            }
        }
        __syncthreads();
    }

#pragma unroll
    for (int mt = 0; mt < 2; mt++) {
        size_t r_hi = row0 + wm + (mt << 4) + g;
#pragma unroll
        for (int nt = 0; nt < 4; nt++) {
            size_t cb = col0 + wn + (nt << 3) + (cq << 1);
            float bv0 = bias ? bias[cb] : 0.f;
            float bv1 = bias ? bias[cb + 1] : 0.f;
#pragma unroll
            for (int rr = 0; rr < 2; rr++) {
                size_t r = r_hi + rr * 8;
                float v0 = acc[mt][nt][rr * 2 + 0] + bv0;
                float v1 = acc[mt][nt][rr * 2 + 1] + bv1;
                float* cp = &C[r * (size_t)N + cb];
                if (EPI == 1) { v0 = rna_tf32_f(gelu_f(v0)); v1 = rna_tf32_f(gelu_f(v1)); }
                if (EPI == 2) { v0 += cp[0]; v1 += cp[1]; }
                cp[0] = v0;
                cp[1] = v1;
            }
        }
    }
#endif
}

// ---------------------------------------------------------------------------
// Embedding
// ---------------------------------------------------------------------------
__global__ void embed_kernel(const int* __restrict__ idxs,
                             const float* __restrict__ lat,
                             const float* __restrict__ lon,
                             const float* __restrict__ sog,
                             const float* __restrict__ cog,
                             const float* __restrict__ pos) {
    int row = blockIdx.x;
    int tid = threadIdx.x;
    int t = row & (SEQ - 1);
#pragma unroll
    for (int e = 0; e < 3; e++) {
        int j = (e << 8) + tid;
        int seg = j / 192;
        int off = j - seg * 192;
        int id = idxs[row * 4 + seg];
        const float* tab = (seg == 0) ? lat : (seg == 1) ? lon : (seg == 2) ? sog : cog;
        g_h[(size_t)row * DMODEL + j] = tab[id * 192 + off] + pos[t * DMODEL + j];
    }
}

// ---------------------------------------------------------------------------
// LayerNorm: one block per row. ROUND=1 -> tf32-round the output (GEMM input).
// ---------------------------------------------------------------------------
template <int ROUND>
__global__ void ln_kernel(const float* __restrict__ in, float* __restrict__ out,
                          const float* __restrict__ gamma, const float* __restrict__ beta) {
    int row = blockIdx.x;
    int tid = threadIdx.x;
    const float* x = in + (size_t)row * DMODEL;
    float v0 = x[tid], v1 = x[tid + 256], v2 = x[tid + 512];

    __shared__ float red[8];
    __shared__ float s_mean, s_rstd;

    float s = v0 + v1 + v2;
#pragma unroll
    for (int o = 16; o; o >>= 1) s += __shfl_xor_sync(0xffffffffu, s, o);
    if ((tid & 31) == 0) red[tid >> 5] = s;
    __syncthreads();
    if (tid == 0) {
        float t = 0.f;
#pragma unroll
        for (int i = 0; i < 8; i++) t += red[i];
        s_mean = t * (1.0f / 768.0f);
    }
    __syncthreads();
    float m = s_mean;
    float d0 = v0 - m, d1 = v1 - m, d2 = v2 - m;
    float q = d0 * d0 + d1 * d1 + d2 * d2;
#pragma unroll
    for (int o = 16; o; o >>= 1) q += __shfl_xor_sync(0xffffffffu, q, o);
    if ((tid & 31) == 0) red[tid >> 5] = q;
    __syncthreads();
    if (tid == 0) {
        float t = 0.f;
#pragma unroll
        for (int i = 0; i < 8; i++) t += red[i];
        s_rstd = rsqrtf(t * (1.0f / 768.0f) + 1e-5f);
    }
    __syncthreads();
    float r = s_rstd;
    float* o_ = out + (size_t)row * DMODEL;
    float w0 = d0 * r * gamma[tid]       + beta[tid];
    float w1 = d1 * r * gamma[tid + 256] + beta[tid + 256];
    float w2 = d2 * r * gamma[tid + 512] + beta[tid + 512];
    if (ROUND) { w0 = rna_tf32_f(w0); w1 = rna_tf32_f(w1); w2 = rna_tf32_f(w2); }
    o_[tid]       = w0;
    o_[tid + 256] = w1;
    o_[tid + 512] = w2;
}

// ---------------------------------------------------------------------------
// SIMT SGEMM for the head (N=302)
// ---------------------------------------------------------------------------
__global__ void sgemm_head_kernel(const float* __restrict__ A, const float* __restrict__ B,
                                  float* __restrict__ C, int M, int N, int K) {
    __shared__ float As[16][65];
    __shared__ float Bs[16][64];
    int tid = threadIdx.x;
    int tx = tid & 15, ty = tid >> 4;
    int row0 = blockIdx.y << 6, col0 = blockIdx.x << 6;
    float acc[4][4] = {};

    for (int k0 = 0; k0 < K; k0 += 16) {
#pragma unroll
        for (int i = tid; i < 1024; i += 256) {
            int r = i >> 4, c = i & 15;
            As[c][r] = A[(size_t)(row0 + r) * K + (k0 + c)];
        }
#pragma unroll
        for (int i = tid; i < 1024; i += 256) {
            int r = i >> 6, c = i & 63;
            int col = col0 + c;
            Bs[r][c] = (col < N) ? B[(size_t)(k0 + r) * N + col] : 0.f;
        }
        __syncthreads();
#pragma unroll
        for (int kk = 0; kk < 16; kk++) {
            float a[4], b[4];
#pragma unroll
            for (int i = 0; i < 4; i++) a[i] = As[kk][ty * 4 + i];
#pragma unroll
            for (int j = 0; j < 4; j++) b[j] = Bs[kk][tx * 4 + j];
#pragma unroll
            for (int i = 0; i < 4; i++)
#pragma unroll
                for (int j = 0; j < 4; j++) acc[i][j] += a[i] * b[j];
        }
        __syncthreads();
    }

#pragma unroll
    for (int i = 0; i < 4; i++) {
        int r = row0 + ty * 4 + i;
#pragma unroll
        for (int j = 0; j < 4; j++) {
            int col = col0 + tx * 4 + j;
            if (col < N) C[(size_t)r * N + col] = acc[i][j];
        }
    }
}

// ---------------------------------------------------------------------------
// QK^T (SIMT, causal tiles only)
// ---------------------------------------------------------------------------
__global__ void qk_kernel(const float* __restrict__ Q, const float* __restrict__ K,
                          float* __restrict__ S) {
    int tq = blockIdx.x >> 2, tk = blockIdx.x & 3;
    if (tk > tq) return;
    int bh = blockIdx.y;
    int b = bh / NHEAD, h = bh % NHEAD;
    const float* Qp = Q + (size_t)b * SEQ * DMODEL + h * HDIM;
    const float* Kp = K + (size_t)b * SEQ * DMODEL + h * HDIM;
    float* Sp = S + (size_t)bh * (SEQ * SEQ);

    __shared__ float As[16][65];
    __shared__ float Bs[16][65];
    int tid = threadIdx.x;
    int tx = tid & 15, ty = tid >> 4;
    int row0 = tq << 6, col0 = tk << 6;
    float acc[4][4] = {};

    for (int k0 = 0; k0 < HDIM; k0 += 16) {
#pragma unroll
        for (int i = tid; i < 1024; i += 256) {
            int r = i >> 4, c = i & 15;
            As[c][r] = Qp[(size_t)(row0 + r) * DMODEL + (k0 + c)];
        }
#pragma unroll
        for (int i = tid; i < 1024; i += 256) {
            int r = i & 15, c = i >> 4;
            Bs[r][c] = Kp[(size_t)(col0 + c) * DMODEL + (k0 + r)];
        }
        __syncthreads();
#pragma unroll
        for (int kk = 0; kk < 16; kk++) {
            float a[4], bb[4];
#pragma unroll
            for (int i = 0; i < 4; i++) a[i] = As[kk][ty * 4 + i];
#pragma unroll
            for (int j = 0; j < 4; j++) bb[j] = Bs[kk][tx * 4 + j];
#pragma unroll
            for (int i = 0; i < 4; i++)
#pragma unroll
                for (int j = 0; j < 4; j++) acc[i][j] += a[i] * bb[j];
        }
        __syncthreads();
    }

#pragma unroll
    for (int i = 0; i < 4; i++)
#pragma unroll
        for (int j = 0; j < 4; j++)
            Sp[(size_t)(row0 + ty * 4 + i) * SEQ + (col0 + tx * 4 + j)] = acc[i][j] * 0.125f;
}

// ---------------------------------------------------------------------------
// Causal softmax in place
// ---------------------------------------------------------------------------
__global__ void softmax_kernel(float* __restrict__ S) {
    int w = (blockIdx.x << 3) + (threadIdx.x >> 5);
    int q = w & (SEQ - 1);
    float* row = S + (size_t)(w >> 8) * (SEQ * SEQ) + (size_t)q * SEQ;
    int lane = threadIdx.x & 31;

    float v[8];
    float mx = -1e30f;
#pragma unroll
    for (int kk = 0; kk < 8; kk++) {
        int k = (kk << 5) + lane;
        float s = (k <= q) ? row[k] : -1e30f;
        v[kk] = s;
        mx = fmaxf(mx, s);
    }
#pragma unroll
    for (int o = 16; o; o >>= 1) mx = fmaxf(mx, __shfl_xor_sync(0xffffffffu, mx, o));
    float sum = 0.f;
#pragma unroll
    for (int kk = 0; kk < 8; kk++) {
        float e = expf(v[kk] - mx);
        v[kk] = e;
        sum += e;
    }
#pragma unroll
    for (int o = 16; o; o >>= 1) sum += __shfl_xor_sync(0xffffffffu, sum, o);
    float inv = 1.0f / sum;
#pragma unroll
    for (int kk = 0; kk < 8; kk++) {
        int k = (kk << 5) + lane;
        row[k] = v[kk] * inv;
    }
}

// ---------------------------------------------------------------------------
// AV (SIMT, causal k-truncation); output tf32-rounded (feeds O-proj GEMM)
// ---------------------------------------------------------------------------
__global__ void av_kernel(const float* __restrict__ S, const float* __restrict__ V,
                          float* __restrict__ Y) {
    int bh = blockIdx.y;
    int b = bh / NHEAD, h = bh % NHEAD;
    const float* Sp = S + (size_t)bh * (SEQ * SEQ);
    const float* Vp = V + (size_t)b * SEQ * DMODEL + h * HDIM;
    float* Yp = Y + (size_t)b * SEQ * DMODEL + h * HDIM;

    __shared__ float As[16][65];
    __shared__ float Bs[16][64];
    int tid = threadIdx.x;
    int tx = tid & 15, ty = tid >> 4;
    int row0 = blockIdx.x << 6;
    int kend = row0 + 64;
    float acc[4][4] = {};

    for (int k0 = 0; k0 < kend; k0 += 16) {
#pragma unroll
        for (int i = tid; i < 1024; i += 256) {
            int r = i >> 4, c = i & 15;
            As[c][r] = Sp[(size_t)(row0 + r) * SEQ + (k0 + c)];
        }
#pragma unroll
        for (int i = tid; i < 1024; i += 256) {
            int r = i >> 6, c = i & 63;
            Bs[r][c] = Vp[(size_t)(k0 + r) * DMODEL + c];
        }
        __syncthreads();
#pragma unroll
        for (int kk = 0; kk < 16; kk++) {
            float a[4], bb[4];
#pragma unroll
            for (int i = 0; i < 4; i++) a[i] = As[kk][ty * 4 + i];
#pragma unroll
            for (int j = 0; j < 4; j++) bb[j] = Bs[kk][tx * 4 + j];
#pragma unroll
            for (int i = 0; i < 4; i++)
#pragma unroll
                for (int j = 0; j < 4; j++) acc[i][j] += a[i] * bb[j];
        }
        __syncthreads();
    }

#pragma unroll
    for (int i = 0; i < 4; i++)
#pragma unroll
        for (int j = 0; j < 4; j++)
            Yp[(size_t)(row0 + ty * 4 + i) * DMODEL + (tx * 4 + j)] =
                rna_tf32_f(acc[i][j]);
}

// ---------------------------------------------------------------------------
// Launch
// ---------------------------------------------------------------------------
extern "C" void kernel_launch(void* const* d_in, const int* in_sizes, int n_in,
                              void* d_out, int out_size) {
    const int*   idxs  = (const int*)  d_in[0];
    const float* lat   = (const float*)d_in[1];
    const float* lon   = (const float*)d_in[2];
    const float* sog   = (const float*)d_in[3];
    const float* cog   = (const float*)d_in[4];
    const float* pos   = (const float*)d_in[5];
    const float* ln1_g = (const float*)d_in[6];
    const float* ln1_b = (const float*)d_in[7];
    const float* ln2_g = (const float*)d_in[8];
    const float* ln2_b = (const float*)d_in[9];
    const float* Wq    = (const float*)d_in[10];
    const float* bq    = (const float*)d_in[11];
    const float* Wk    = (const float*)d_in[12];
    const float* bk    = (const float*)d_in[13];
    const float* Wv    = (const float*)d_in[14];
    const float* bv    = (const float*)d_in[15];
    const float* Wo    = (const float*)d_in[16];
    const float* bo    = (const float*)d_in[17];
    const float* W1    = (const float*)d_in[18];
    const float* b1    = (const float*)d_in[19];
    const float* W2    = (const float*)d_in[20];
    const float* b2    = (const float*)d_in[21];
    const float* lnf_g = (const float*)d_in[22];
    const float* lnf_b = (const float*)d_in[23];
    const float* Whead = (const float*)d_in[24];
    float* out = (float*)d_out;

    float *hb, *xb, *qb, *kb, *vb, *yb, *sb, *wt;
    cudaGetSymbolAddress((void**)&hb, g_h);
    cudaGetSymbolAddress((void**)&xb, g_x);
    cudaGetSymbolAddress((void**)&qb, g_q);
    cudaGetSymbolAddress((void**)&kb, g_k);
    cudaGetSymbolAddress((void**)&vb, g_v);
    cudaGetSymbolAddress((void**)&yb, g_y);
    cudaGetSymbolAddress((void**)&sb, g_s);
    cudaGetSymbolAddress((void**)&wt, g_wt);

    const size_t DD = (size_t)DMODEL * DMODEL;     // 589824
    const size_t DF = (size_t)DMODEL * DFF;        // 2359296
    const size_t DD12 = DD * NLAYER;               // 7077888
    float* Wq_t = wt;
    float* Wk_t = wt + DD12;
    float* Wv_t = wt + 2 * DD12;
    float* Wo_t = wt + 3 * DD12;
    float* W1_t = wt + 4 * DD12;                   // [12][3072][768]
    float* W2_t = wt + 4 * DD12 + DF * NLAYER;     // [12][768][3072]

    const int GEMM_SMEM = 1024 + 65536;
    cudaFuncSetAttribute(tc_gemm<0>, cudaFuncAttributeMaxDynamicSharedMemorySize, GEMM_SMEM);
    cudaFuncSetAttribute(tc_gemm<1>, cudaFuncAttributeMaxDynamicSharedMemorySize, GEMM_SMEM);
    cudaFuncSetAttribute(tc_gemm<2>, cudaFuncAttributeMaxDynamicSharedMemorySize, GEMM_SMEM);

    // launch 0: all weight transposes in one kernel
    {
        dim3 blk(32, 8);
        dim3 grd(96, 24, 72);
        transpose_all_kernel<<<grd, blk>>>(Wq, Wk, Wv, Wo, W1, W2, wt);
    }
    // launch 1
    embed_kernel<<<M_ROWS, 256>>>(idxs, lat, lon, sog, cog, pos);

    dim3 gD(DMODEL / 128, M_ROWS / 128);     // (6, 128)
    dim3 gF(DFF / 128, M_ROWS / 128);        // (24, 128)
    dim3 gQK(16, NHEAD * 64);
    dim3 gAV(4, NHEAD * 64);
    dim3 gHead((NOUT + 63) / 64, M_ROWS / 64);

    for (int l = 0; l < NLAYER; l++) {
        // launches 2,3,4,5 in layer 0: ln, Q, K, V  (ncu -s 5 captures V gemm)
        ln_kernel<1><<<M_ROWS, 256>>>(hb, xb, ln1_g + l * DMODEL, ln1_b + l * DMODEL);
        tc_gemm<0><<<gD, 512, GEMM_SMEM>>>(xb, Wq_t + l * DD, bq + l * DMODEL, qb, M_ROWS, DMODEL, DMODEL);
        tc_gemm<0><<<gD, 512, GEMM_SMEM>>>(xb, Wk_t + l * DD, bk + l * DMODEL, kb, M_ROWS, DMODEL, DMODEL);
        tc_gemm<0><<<gD, 512, GEMM_SMEM>>>(xb, Wv_t + l * DD, bv + l * DMODEL, vb, M_ROWS, DMODEL, DMODEL);
        qk_kernel<<<gQK, 256>>>(qb, kb, sb);
        softmax_kernel<<<(NHEAD * 64 * SEQ) / 8, 256>>>(sb);
        av_kernel<<<gAV, 256>>>(sb, vb, yb);
        tc_gemm<2><<<gD, 512, GEMM_SMEM>>>(yb, Wo_t + l * DD, bo + l * DMODEL, hb, M_ROWS, DMODEL, DMODEL);
        ln_kernel<1><<<M_ROWS, 256>>>(hb, xb, ln2_g + l * DMODEL, ln2_b + l * DMODEL);
        tc_gemm<1><<<gF, 512, GEMM_SMEM>>>(xb, W1_t + l * DF, b1 + l * DFF, sb, M_ROWS, DFF, DMODEL);
        tc_gemm<2><<<gD, 512, GEMM_SMEM>>>(sb, W2_t + l * DF, b2 + l * DMODEL, hb, M_ROWS, DMODEL, DFF);
    }

    ln_kernel<0><<<M_ROWS, 256>>>(hb, xb, lnf_g, lnf_b);
    sgemm_head_kernel<<<gHead, 256>>>(xb, Whead, out, M_ROWS, NOUT, DMODEL);
}